// round 4
// baseline (speedup 1.0000x reference)
#include <cuda_runtime.h>
#include <math.h>

// Problem constants
#define BATCH 2
#define SLEN  2048
#define NH    32
#define HD    32
#define DM    (NH*HD)        // 1024
#define M_GEMM (BATCH*SLEN)  // 4096
#define N_GEMM (3*DM)        // 3072
#define K_GEMM DM            // 1024

// Scratch (device globals; no allocation allowed)
__device__ float g_qkv[(size_t)M_GEMM * N_GEMM];        // [4096, 3072]
__device__ float g_q[(size_t)BATCH*NH*SLEN*HD];         // [64, 2048, 32]
__device__ float g_k[(size_t)BATCH*NH*SLEN*HD];
__device__ float g_v[(size_t)BATCH*NH*SLEN*HD];

// ---------------------------------------------------------------------------
// Kernel 1: QKV GEMM  C[M,N] = A[M,K] * B[K,N]   (fp32, 128x128x16 tiles)
// ---------------------------------------------------------------------------
__global__ __launch_bounds__(256) void qkv_gemm_kernel(
    const float* __restrict__ A, const float* __restrict__ B)
{
    __shared__ float As[16][128];   // As[k][m]
    __shared__ float Bs[16][128];   // Bs[k][n]

    const int tid = threadIdx.x;          // 0..255
    const int bx  = blockIdx.x;           // N tile (24)
    const int by  = blockIdx.y;           // M tile (32)

    const int tx = tid & 15;              // 0..15
    const int ty = tid >> 4;              // 0..15

    // A-load mapping: 128 rows x 16 cols = 512 float4, 2 per thread
    const int a_r = tid >> 2;             // 0..63
    const int a_c = (tid & 3) << 2;       // 0,4,8,12
    // B-load mapping: 16 rows x 128 cols = 512 float4, 2 per thread
    const int b_r = tid >> 5;             // 0..7
    const int b_c = (tid & 31) << 2;      // 0..124

    float acc[8][8];
    #pragma unroll
    for (int i = 0; i < 8; i++)
        #pragma unroll
        for (int j = 0; j < 8; j++) acc[i][j] = 0.f;

    const float* Ab = A + (size_t)(by * 128) * K_GEMM;
    const float* Bb = B + bx * 128;

    for (int k0 = 0; k0 < K_GEMM; k0 += 16) {
        // load A tile (transposed into As[k][m])
        #pragma unroll
        for (int half = 0; half < 2; half++) {
            int r = a_r + half * 64;
            float4 v = *(const float4*)(Ab + (size_t)r * K_GEMM + k0 + a_c);
            As[a_c + 0][r] = v.x;
            As[a_c + 1][r] = v.y;
            As[a_c + 2][r] = v.z;
            As[a_c + 3][r] = v.w;
        }
        // load B tile
        #pragma unroll
        for (int half = 0; half < 2; half++) {
            int r = b_r + half * 8;
            float4 v = *(const float4*)(Bb + (size_t)(k0 + r) * N_GEMM + b_c);
            *(float4*)&Bs[r][b_c] = v;
        }
        __syncthreads();

        #pragma unroll
        for (int k = 0; k < 16; k++) {
            float a[8], b[8];
            float4 a0 = *(const float4*)&As[k][ty * 8];
            float4 a1 = *(const float4*)&As[k][ty * 8 + 4];
            float4 b0 = *(const float4*)&Bs[k][tx * 8];
            float4 b1 = *(const float4*)&Bs[k][tx * 8 + 4];
            a[0]=a0.x; a[1]=a0.y; a[2]=a0.z; a[3]=a0.w;
            a[4]=a1.x; a[5]=a1.y; a[6]=a1.z; a[7]=a1.w;
            b[0]=b0.x; b[1]=b0.y; b[2]=b0.z; b[3]=b0.w;
            b[4]=b1.x; b[5]=b1.y; b[6]=b1.z; b[7]=b1.w;
            #pragma unroll
            for (int i = 0; i < 8; i++)
                #pragma unroll
                for (int j = 0; j < 8; j++)
                    acc[i][j] += a[i] * b[j];
        }
        __syncthreads();
    }

    // write back
    #pragma unroll
    for (int i = 0; i < 8; i++) {
        size_t row = (size_t)(by * 128 + ty * 8 + i);
        float* Cp = g_qkv + row * N_GEMM + bx * 128 + tx * 8;
        float4 v0 = make_float4(acc[i][0], acc[i][1], acc[i][2], acc[i][3]);
        float4 v1 = make_float4(acc[i][4], acc[i][5], acc[i][6], acc[i][7]);
        *(float4*)(Cp)     = v0;
        *(float4*)(Cp + 4) = v1;
    }
}

// ---------------------------------------------------------------------------
// Kernel 2: RoPE + scatter into [B*H, S, D] layouts
// ---------------------------------------------------------------------------
__global__ void rope_scatter_kernel()
{
    int idx = blockIdx.x * blockDim.x + threadIdx.x;   // B*S*H*D = 4194304
    if (idx >= BATCH * SLEN * NH * HD) return;
    int d = idx & 31;
    int h = (idx >> 5) & 31;
    int s = (idx >> 10) & (SLEN - 1);
    int b = idx >> 21;

    size_t row = (size_t)(b * SLEN + s) * N_GEMM;
    int col = h * HD + d;

    float qv = g_qkv[row + col];
    float kv = g_qkv[row + DM + col];
    float vv = g_qkv[row + 2 * DM + col];

    int   dp  = (d < 16) ? d + 16 : d - 16;
    float sgn = (d < 16) ? -1.f : 1.f;
    float qp = sgn * g_qkv[row + h * HD + dp];
    float kp = sgn * g_qkv[row + DM + h * HD + dp];

    // inv_freq = 10000^(-d/32); freq = s * inv_freq  (reference uses full-dim stride)
    float inv_freq = exp2f(-((float)d / 32.f) * 13.28771237954945f); // log2(10000)
    float fr = (float)s * inv_freq;
    float sn, cs;
    sincosf(fr, &sn, &cs);

    float qo = qv * cs + qp * sn;
    float ko = kv * cs + kp * sn;

    size_t o = ((size_t)(b * NH + h) * SLEN + s) * HD + d;
    g_q[o] = qo;
    g_k[o] = ko;
    g_v[o] = vv;
}

// ---------------------------------------------------------------------------
// Kernel 3: causal flash attention.  64 threads/block, 2 q-rows per thread.
// Grid: (S/128, B*H)
// ---------------------------------------------------------------------------
__global__ __launch_bounds__(64) void attn_kernel(float* __restrict__ O)
{
    const int bh = blockIdx.y;            // 0..63
    const int q0 = blockIdx.x * 128;
    const int t  = threadIdx.x;           // 0..63
    const int b  = bh >> 5;
    const int h  = bh & 31;
    const float scale = 0.17677669529663687f;  // 1/sqrt(32)

    __shared__ float Ks[64][32];
    __shared__ float Vs[64][32];

    const float* Qb = g_q + (size_t)bh * SLEN * HD;
    const float* Kb = g_k + (size_t)bh * SLEN * HD;
    const float* Vb = g_v + (size_t)bh * SLEN * HD;

    const int r0 = q0 + t;
    const int r1 = r0 + 64;

    float q0r[32], q1r[32], acc0[32], acc1[32];
    #pragma unroll
    for (int d = 0; d < 32; d++) {
        q0r[d] = Qb[(size_t)r0 * HD + d] * scale;
        q1r[d] = Qb[(size_t)r1 * HD + d] * scale;
        acc0[d] = 0.f; acc1[d] = 0.f;
    }
    float m0 = -1e30f, m1 = -1e30f, l0 = 0.f, l1 = 0.f;

    const int ntiles = q0 / 64 + 2;   // covers kj up to r1 max
    for (int kt = 0; kt < ntiles; kt++) {
        const int kbase = kt * 64;
        __syncthreads();
        {
            const float4* ksrc = (const float4*)(Kb + (size_t)kbase * HD);
            const float4* vsrc = (const float4*)(Vb + (size_t)kbase * HD);
            float4* kdst = (float4*)&Ks[0][0];
            float4* vdst = (float4*)&Vs[0][0];
            #pragma unroll
            for (int i = 0; i < 8; i++) {
                kdst[t + 64 * i] = ksrc[t + 64 * i];
                vdst[t + 64 * i] = vsrc[t + 64 * i];
            }
        }
        __syncthreads();

        #pragma unroll 1
        for (int j = 0; j < 64; j++) {
            const int kj = kbase + j;
            float s0 = 0.f, s1 = 0.f;
            #pragma unroll
            for (int d = 0; d < 32; d++) {
                float kvv = Ks[j][d];
                s0 += q0r[d] * kvv;
                s1 += q1r[d] * kvv;
            }
            if (kj <= r0) {
                if (s0 > m0) {
                    float c = __expf(m0 - s0);
                    l0 *= c;
                    #pragma unroll
                    for (int d = 0; d < 32; d++) acc0[d] *= c;
                    m0 = s0;
                }
                float p = __expf(s0 - m0);
                l0 += p;
                #pragma unroll
                for (int d = 0; d < 32; d++) acc0[d] += p * Vs[j][d];
            }
            if (kj <= r1) {
                if (s1 > m1) {
                    float c = __expf(m1 - s1);
                    l1 *= c;
                    #pragma unroll
                    for (int d = 0; d < 32; d++) acc1[d] *= c;
                    m1 = s1;
                }
                float p = __expf(s1 - m1);
                l1 += p;
                #pragma unroll
                for (int d = 0; d < 32; d++) acc1[d] += p * Vs[j][d];
            }
        }
    }

    const float inv0 = 1.f / l0, inv1 = 1.f / l1;
    float* O0 = O + ((size_t)(b * SLEN + r0)) * DM + h * HD;
    float* O1 = O + ((size_t)(b * SLEN + r1)) * DM + h * HD;
    #pragma unroll
    for (int d = 0; d < 32; d++) {
        O0[d] = acc0[d] * inv0;
        O1[d] = acc1[d] * inv1;
    }
}

// ---------------------------------------------------------------------------
extern "C" void kernel_launch(void* const* d_in, const int* in_sizes, int n_in,
                              void* d_out, int out_size)
{
    const float* x     = (const float*)d_in[0];   // [2, 2048, 1024]
    const float* W_qkv = (const float*)d_in[1];   // [1024, 3072]
    // d_in[2] = causal mask (ignored; causality hard-coded)
    float* out = (float*)d_out;                   // [2, 2048, 1024]

    {
        dim3 grid(N_GEMM / 128, M_GEMM / 128);
        qkv_gemm_kernel<<<grid, 256>>>(x, W_qkv);
    }
    {
        int total = BATCH * SLEN * NH * HD;
        rope_scatter_kernel<<<(total + 255) / 256, 256>>>();
    }
    {
        dim3 grid(SLEN / 128, BATCH * NH);
        attn_kernel<<<grid, 64>>>(out);
    }
}